// round 7
// baseline (speedup 1.0000x reference)
#include <cuda_runtime.h>
#include <math.h>

#define BB 2
#define SS 4096
#define DM 768
#define HH 12
#define HD 64
#define OUTN 512
#define GRID 256
#define NTHR 512
#define CHROWS 32
#define NCH (SS/CHROWS)     // 128 chunks per batch; BB*NCH = 256 = GRID

// ---------------- scratch ---------------------------------------------------
__device__ float g_qg[BB*DM];                 // scaled q row0
__device__ float g_u[BB*DM*HH];               // folded key weights [b][m][h]
__device__ float g_denom[BB*HH];
__device__ float g_ypart[NCH*BB*HH*DM];       // per-chunk partial sums (9.4MB)
__device__ float g_og[BB*DM];                 // init bvg, atomic accum
__device__ float g_part1[BB*DM];              // init bo,  atomic accum
__device__ float g_part2[BB*DM];              // init bp,  atomic accum
__device__ unsigned g_bar[8];                 // monotonic per-stage counters

// ---------------- f32x2 helpers ---------------------------------------------
#define FMA2(d,a,b,c) asm("fma.rn.f32x2 %0, %1, %2, %3;" : "=l"(d) : "l"(a), "l"(b), "l"(c))
#define PACK2(d,lo,hi) asm("mov.b64 %0, {%1,%2};" : "=l"(d) : "f"(lo), "f"(hi))
#define UNPK2(lo,hi,s) asm("mov.b64 {%0,%1}, %2;" : "=f"(lo), "=f"(hi) : "l"(s))

// ---------------- grid barrier: release-add / acquire-poll, per-stage count -
__device__ __forceinline__ void gbar(int id, unsigned expect) {
    __syncthreads();
    if (threadIdx.x == 0) {
        unsigned arr;
        asm volatile("atom.release.gpu.global.add.u32 %0, [%1], 1;"
                     : "=r"(arr) : "l"(g_bar + id) : "memory");
        unsigned target = (arr / expect + 1u) * expect;
        unsigned cur;
        asm volatile("ld.acquire.gpu.global.u32 %0, [%1];"
                     : "=r"(cur) : "l"(g_bar + id) : "memory");
        while (cur < target) {
            __nanosleep(20);
            asm volatile("ld.acquire.gpu.global.u32 %0, [%1];"
                         : "=r"(cur) : "l"(g_bar + id) : "memory");
        }
    }
    __syncthreads();
}

__global__ __launch_bounds__(NTHR, 2)
void k_mega(const float* __restrict__ x,   const float* __restrict__ wqg,
            const float* __restrict__ bqg, const float* __restrict__ wkg,
            const float* __restrict__ wvg, const float* __restrict__ bvg,
            const float* __restrict__ wo,  const float* __restrict__ bo,
            const float* __restrict__ wp,  const float* __restrict__ bp,
            const float* __restrict__ wfc, const float* __restrict__ bfc,
            float* __restrict__ out) {
    __shared__ __align__(16) float sm[9984];   // ~39 KB union, per-stage reuse
    const int blk = blockIdx.x;
    const int t = threadIdx.x;

    // ======== Stage 0: inits + qg (blocks 0..23) + weight L2 prefetch =======
    {
        int j = blk*NTHR + t;
        if (j < 1536)       g_og[j]         = bvg[j % DM];
        else if (j < 3072)  g_part1[j-1536] = bo[(j-1536) % DM];
        else if (j < 4608)  g_part2[j-3072] = bp[(j-3072) % DM];
        else if (j < 5632)  out[j-4608]     = bfc[(j-4608) % OUTN];
        else if (j < 5656)  g_denom[j-5632] = 0.f;
    }
    if (blk < 24) {
        int b = blk / 12, h = blk % 12;
        float* x0s = sm; float* redA = sm + 768;
        for (int i = t; i < DM; i += NTHR) x0s[i] = x[(size_t)b*SS*DM + i];
        __syncthreads();
        int o = t & 63, part = t >> 6;                 // 8 parts of 96 m
        float acc = 0.f;
        const float* wc = wqg + h*HD + o;
        #pragma unroll 16
        for (int j = 0; j < 96; j++) {
            int m = part*96 + j;
            acc += x0s[m] * wc[(size_t)m*DM];
        }
        redA[t] = acc;
        __syncthreads();
        if (t < 64) {
            float s = bqg[h*HD + t];
            #pragma unroll
            for (int k = 0; k < 8; k++) s += redA[k*64 + t];
            g_qg[b*DM + h*HD + t] = s * 0.125f;
        }
    } else {
        // Fire-and-forget L2 prefetch of tail-stage weights (8.25 MB total).
        // 232 blocks x 512 thr, ~5 float4 loads each; results unused, lands in L2.
        const int W = DM*DM/4;        // 147456 float4 per 768x768 matrix
        const int TOT = 3*W + OUTN*DM/4;
        int idx0 = (blk - 24)*NTHR + t;
        for (int idx = idx0; idx < TOT; idx += 232*NTHR) {
            const float4* p;
            if (idx < W)            p = (const float4*)wvg + idx;
            else if (idx < 2*W)     p = (const float4*)wo  + (idx -   W);
            else if (idx < 3*W)     p = (const float4*)wp  + (idx - 2*W);
            else                    p = (const float4*)wfc + (idx - 3*W);
            float4 v;
            asm volatile("ld.global.cg.v4.f32 {%0,%1,%2,%3}, [%4];"
                         : "=f"(v.x), "=f"(v.y), "=f"(v.z), "=f"(v.w) : "l"(p));
        }
    }
    gbar(0, GRID);

    // ======== Stage 1: u[b,m,h] = qg[b,h,:]·wkg[m,h*64:] (blocks 0..127) ====
    if (blk < 128) {
        int b = blk >> 6, mc = blk & 63;     // 12 m's per block
        float* qgs = sm;
        for (int i = t; i < DM; i += NTHR) qgs[i] = g_qg[b*DM + i];
        __syncthreads();
        if (t < 144) {
            int mi = t / 12, h = t % 12;
            int m = mc*12 + mi;
            const float* w = wkg + (size_t)m*DM + h*HD;
            const float* q = qgs + h*HD;
            float acc = 0.f;
            #pragma unroll
            for (int d = 0; d < HD; d++) acc += q[d] * w[d];
            g_u[((size_t)b*DM + m)*HH + h] = acc;
        }
    }
    gbar(1, GRID);

    // ======== Stage 2: fused scores -> exp -> weighted-sum partials =========
    {
        int b = blk >> 7, ch = blk & (NCH-1);
        int s0 = ch * CHROWS;
        float* u_s = sm;                 // [m][12], 9216 floats
        float* e_s = sm + 9216;          // [s][12], 384 floats
        float* stg = sm + 9600;          // [row][12] cross-half staging
        {
            const float4* src = (const float4*)(g_u + (size_t)b*DM*HH);
            float4* dst = (float4*)u_s;
            for (int i = t; i < DM*HH/4; i += NTHR) dst[i] = src[i];
        }
        __syncthreads();

        // ---- phase 1: 32 rows x 8 lanes x 2 m-halves, f32x2 head pairs
        {
            int mh = t >> 8, rw = (t & 255) >> 3, p = t & 7;
            const float* xr = x + ((size_t)b*SS + s0 + rw)*DM + mh*384;
            unsigned long long aA[6];
            #pragma unroll
            for (int k = 0; k < 6; k++) aA[k] = 0ull;
            #pragma unroll 8
            for (int i = 0; i < 48; i++) {
                int ml = i*8 + p;
                float xv = xr[ml];
                unsigned long long xx;
                PACK2(xx, xv, xv);
                const ulonglong2* u2p = (const ulonglong2*)(u_s + (mh*384 + ml)*HH);
                ulonglong2 w0 = u2p[0], w1 = u2p[1], w2 = u2p[2];
                FMA2(aA[0], xx, w0.x, aA[0]); FMA2(aA[1], xx, w0.y, aA[1]);
                FMA2(aA[2], xx, w1.x, aA[2]); FMA2(aA[3], xx, w1.y, aA[3]);
                FMA2(aA[4], xx, w2.x, aA[4]); FMA2(aA[5], xx, w2.y, aA[5]);
            }
            float vA[12];
            #pragma unroll
            for (int k = 0; k < 6; k++) UNPK2(vA[2*k], vA[2*k+1], aA[k]);
            #pragma unroll
            for (int off = 4; off; off >>= 1)
                #pragma unroll
                for (int h = 0; h < HH; h++)
                    vA[h] += __shfl_down_sync(0xffffffffu, vA[h], off, 8);
            if (p == 0 && mh == 1) {
                #pragma unroll
                for (int h = 0; h < HH; h++) stg[rw*HH + h] = vA[h];
            }
            __syncthreads();
            if (p == 0 && mh == 0) {
                #pragma unroll
                for (int h = 0; h < HH; h++)
                    e_s[rw*HH + h] = __expf(vA[h] + stg[rw*HH + h]);
            }
        }
        __syncthreads();

        // ---- denominator partials
        if (t < HH) {
            float s = 0.f;
            #pragma unroll 8
            for (int j = 0; j < CHROWS; j++) s += e_s[j*HH + t];
            atomicAdd(&g_denom[b*HH + t], s);
        }

        // ---- phase 2: head-split; ypart[h][m] = sum_s e[s][h]*x[s][m]
        {
            int hh = t >> 8, tc = t & 255;
            unsigned long long acc[3][3];
            #pragma unroll
            for (int c = 0; c < 3; c++)
                #pragma unroll
                for (int k = 0; k < 3; k++) acc[c][k] = 0ull;
            const float* xp = x + ((size_t)b*SS + s0)*DM;
            for (int s = 0; s < CHROWS; s++) {
                float xv0 = xp[(size_t)s*DM + tc];
                float xv1 = xp[(size_t)s*DM + 256 + tc];
                float xv2 = xp[(size_t)s*DM + 512 + tc];
                unsigned long long xx0, xx1, xx2;
                PACK2(xx0, xv0, xv0); PACK2(xx1, xv1, xv1); PACK2(xx2, xv2, xv2);
                const unsigned long long* ep =
                    (const unsigned long long*)(e_s + s*HH + hh*6);
                unsigned long long e0 = ep[0], e1 = ep[1], e2 = ep[2];
                FMA2(acc[0][0], e0, xx0, acc[0][0]);
                FMA2(acc[0][1], e1, xx0, acc[0][1]);
                FMA2(acc[0][2], e2, xx0, acc[0][2]);
                FMA2(acc[1][0], e0, xx1, acc[1][0]);
                FMA2(acc[1][1], e1, xx1, acc[1][1]);
                FMA2(acc[1][2], e2, xx1, acc[1][2]);
                FMA2(acc[2][0], e0, xx2, acc[2][0]);
                FMA2(acc[2][1], e1, xx2, acc[2][1]);
                FMA2(acc[2][2], e2, xx2, acc[2][2]);
            }
            size_t base = ((size_t)ch*BB + b)*HH + hh*6;
            #pragma unroll
            for (int c = 0; c < 3; c++)
                #pragma unroll
                for (int k = 0; k < 3; k++) {
                    float f0, f1;
                    UNPK2(f0, f1, acc[c][k]);
                    g_ypart[(base + 2*k  )*DM + c*256 + tc] = f0;
                    g_ypart[(base + 2*k+1)*DM + c*256 + tc] = f1;
                }
        }
    }
    gbar(2, GRID);
    if (blk >= 192) return;                 // not needed downstream

    // ======== Stage 3: og = (y/denom) @ wvg slice (192 blocks) ==============
    {
        int b = blk / 96; int r = blk % 96;
        int h = r >> 3; int sub = r & 7;                 // 8 subs of 96 m
        float* redR = sm;            // 384
        float* y_s  = sm + 384;      // 96
        float* redG = sm + 512;      // 512
        float inv = 1.f / __ldcg(&g_denom[b*HH + h]);
        {
            int prt = t >> 7, e = t & 127;
            if (e < 96) {
                float s = 0.f;
                #pragma unroll 8
                for (int c2 = prt*32; c2 < prt*32 + 32; c2++)
                    s += g_ypart[(((size_t)c2*BB + b)*HH + h)*DM + sub*96 + e];
                redR[prt*96 + e] = s;
            }
        }
        __syncthreads();
        if (t < 96) y_s[t] = (redR[t] + redR[96+t] + redR[192+t] + redR[288+t]) * inv;
        __syncthreads();
        int o = t & 63, q = t >> 6;          // 8 parts of 12 m
        float acc = 0.f;
        const float* wc = wvg + h*HD + o;
        #pragma unroll
        for (int j = 0; j < 12; j++) {
            int ml = q*12 + j;
            acc += y_s[ml] * wc[(size_t)(sub*96 + ml)*DM];
        }
        redG[t] = acc;
        __syncthreads();
        if (t < 64) {
            float s = 0.f;
            #pragma unroll
            for (int k = 0; k < 8; k++) s += redG[k*64 + t];
            atomicAdd(&g_og[b*DM + h*HD + t], s);
        }
    }
    gbar(3, 192);
    if (blk >= 144) return;                 // not needed downstream

    // ======== Stage 4: attn0 partials: og @ wo (144 blocks) =================
    {
        int b = blk / 72; int r = blk % 72;
        int oc = r / 24;  int mcp = r % 24;      // 32-m chunk
        float* in_s = sm;
        if (t < 32) in_s[t] = __ldcg(&g_og[b*DM + mcp*32 + t]);
        __syncthreads();
        int o = oc*256 + (t & 255), mh = t >> 8;
        float acc = 0.f;
        const float* wc = wo + o;
        #pragma unroll
        for (int j = 0; j < 16; j++)
            acc += in_s[mh*16 + j] * wc[(size_t)(mcp*32 + mh*16 + j)*DM];
        atomicAdd(&g_part1[b*DM + o], acc);
    }
    gbar(4, 144);

    // ======== Stage 5: pre-tanh pooled partials: attn0 @ wp =================
    {
        int b = blk / 72; int r = blk % 72;
        int oc = r / 24;  int mcp = r % 24;
        float* in_s = sm;
        __syncthreads();
        if (t < 32) in_s[t] = __ldcg(&g_part1[b*DM + mcp*32 + t]);
        __syncthreads();
        int o = oc*256 + (t & 255), mh = t >> 8;
        float acc = 0.f;
        const float* wc = wp + o;
        #pragma unroll
        for (int j = 0; j < 16; j++)
            acc += in_s[mh*16 + j] * wc[(size_t)(mcp*32 + mh*16 + j)*DM];
        atomicAdd(&g_part2[b*DM + o], acc);
    }
    gbar(5, 144);
    if (blk >= 96) return;                  // not needed downstream

    // ======== Stage 6: out += tanh(part2) @ wfc (96 blocks) =================
    {
        int b = blk / 48; int r = blk % 48;
        int oc = r / 24;  int mcp = r % 24;
        float* in_s = sm;
        if (t < 32) in_s[t] = tanhf(__ldcg(&g_part2[b*DM + mcp*32 + t]));
        __syncthreads();
        int o = oc*256 + (t & 255), mh = t >> 8;
        float acc = 0.f;
        const float* wc = wfc + o;
        #pragma unroll
        for (int j = 0; j < 16; j++)
            acc += in_s[mh*16 + j] * wc[(size_t)(mcp*32 + mh*16 + j)*OUTN];
        atomicAdd(&out[b*OUTN + o], acc);
    }
}

// ---------------- launch ----------------------------------------------------
extern "C" void kernel_launch(void* const* d_in, const int* in_sizes, int n_in,
                              void* d_out, int out_size) {
    const float* x   = (const float*)d_in[0];
    const float* wqg = (const float*)d_in[7];
    const float* bqg = (const float*)d_in[8];
    const float* wkg = (const float*)d_in[9];
    const float* wvg = (const float*)d_in[11];
    const float* bvg = (const float*)d_in[12];
    const float* wo  = (const float*)d_in[13];
    const float* bo  = (const float*)d_in[14];
    const float* wp  = (const float*)d_in[15];
    const float* bp  = (const float*)d_in[16];
    const float* wfc = (const float*)d_in[17];
    const float* bfc = (const float*)d_in[18];
    float* out = (float*)d_out;

    k_mega<<<GRID, NTHR>>>(x, wqg, bqg, wkg, wvg, bvg, wo, bo, wp, bp, wfc, bfc, out);
}

// round 8
// speedup vs baseline: 1.4225x; 1.4225x over previous
#include <cuda_runtime.h>
#include <math.h>

#define BB 2
#define SS 4096
#define DM 768
#define HH 12
#define OUTN 512
#define GRID 128
#define NTHR 512
#define CHROWS 32
#define CPB 2                  // chunks per block
#define XPAD 772               // x_s row stride in floats (bank-skew pad)

// ---------------- scratch ---------------------------------------------------
__device__ float g_qg[BB*DM];
__device__ float g_u[BB*HH*DM];          // folded key weights, [b][h][m]
__device__ float g_denom[BB*HH];
__device__ float g_y[GRID*HH*DM];        // per-block partial y [slot][h][m]
__device__ float g_og[BB*DM];            // init bvg, atomic accum
__device__ float g_part1[BB*DM];         // init bo,  atomic accum
__device__ float g_part2[BB*DM];         // init bp,  atomic accum
__device__ unsigned g_cnt;               // monotonic grid-barrier counter

// ---------------- f32x2 helpers ---------------------------------------------
#define FMA2(d,a,b,c) asm("fma.rn.f32x2 %0, %1, %2, %3;" : "=l"(d) : "l"(a), "l"(b), "l"(c))
#define PACK2(d,lo,hi) asm("mov.b64 %0, {%1,%2};" : "=l"(d) : "f"(lo), "f"(hi))
#define UNPK2(lo,hi,s) asm("mov.b64 {%0,%1}, %2;" : "=f"(lo), "=f"(hi) : "l"(s))

// ---------------- grid barrier (monotonic counter; replay-safe) -------------
__device__ __forceinline__ void gbar() {
    __syncthreads();
    if (threadIdx.x == 0) {
        __threadfence();
        unsigned arr = atomicAdd(&g_cnt, 1u);
        unsigned target = (arr / GRID + 1u) * GRID;
        while (*((volatile unsigned*)&g_cnt) < target) __nanosleep(32);
        __threadfence();
    }
    __syncthreads();
}

__global__ __launch_bounds__(NTHR, 1)
void k_mega(const float* __restrict__ x,   const float* __restrict__ wqg,
            const float* __restrict__ bqg, const float* __restrict__ wkg,
            const float* __restrict__ wvg, const float* __restrict__ bvg,
            const float* __restrict__ wo,  const float* __restrict__ bo,
            const float* __restrict__ wp,  const float* __restrict__ bp,
            const float* __restrict__ wfc, const float* __restrict__ bfc,
            float* __restrict__ out) {
    extern __shared__ __align__(16) float sm[];
    float* u_s = sm;                     // 9216 floats  [h][m]
    float* x_s = sm + 9216;              // 32*772 = 24704 floats
    float* e_s = sm + 9216 + 24704;      // 384 floats   [s][h]
    const int blk = blockIdx.x;
    const int t = threadIdx.x;

    // ======== Stage 0: accumulator inits + qg (blocks 0..23) ================
    {
        int j = blk*NTHR + t;
        if (j < 1536)       g_og[j]         = bvg[j % DM];
        else if (j < 3072)  g_part1[j-1536] = bo[(j-1536) % DM];
        else if (j < 4608)  g_part2[j-3072] = bp[(j-3072) % DM];
        else if (j < 5632)  out[j-4608]     = bfc[(j-4608) % OUTN];
        else if (j < 5656)  g_denom[j-5632] = 0.f;
    }
    if (blk < 24) {
        int b = blk / 12, h = blk % 12;
        float* x0s = sm; float* redA = sm + 768;
        for (int i = t; i < DM; i += NTHR) x0s[i] = x[(size_t)b*SS*DM + i];
        __syncthreads();
        int o = t & 63, part = t >> 6;                 // 8 parts of 96 m
        float acc = 0.f;
        const float* wc = wqg + h*64 + o;
        #pragma unroll 16
        for (int j = 0; j < 96; j++) {
            int m = part*96 + j;
            acc += x0s[m] * wc[(size_t)m*DM];
        }
        redA[t] = acc;
        __syncthreads();
        if (t < 64) {
            float s = bqg[h*64 + t];
            #pragma unroll
            for (int k = 0; k < 8; k++) s += redA[k*64 + t];
            g_qg[b*DM + h*64 + t] = s * 0.125f;
        }
    }
    gbar();

    // ======== Stage 1: u[b,h,m] = qg[b,h,:]·wkg[m,h*64:] ====================
    {
        int b = blk >> 6, mc = blk & 63;     // 12 m's per block
        float* qgs = sm;
        for (int i = t; i < DM; i += NTHR) qgs[i] = g_qg[b*DM + i];
        __syncthreads();
        if (t < 144) {
            int mi = t / 12, h = t % 12;
            int m = mc*12 + mi;
            const float* w = wkg + (size_t)m*DM + h*64;
            const float* q = qgs + h*64;
            float acc = 0.f;
            #pragma unroll
            for (int d = 0; d < 64; d++) acc += q[d] * w[d];
            g_u[((size_t)b*HH + h)*DM + m] = acc;       // transposed [b][h][m]
        }
    }
    gbar();

    // ======== Stage 2: fused scores -> exp -> weighted sums (2 chunks) ======
    {
        int b = blk >> 6;
        int cb = (blk & 63) * CPB;
        {
            const float4* src = (const float4*)(g_u + (size_t)b*HH*DM);
            float4* dst = (float4*)u_s;
            for (int i = t; i < HH*DM/4; i += NTHR) dst[i] = src[i];
        }
        // persistent phase-2 accumulators (head-split) and denom partial
        const int hh = t >> 8, tc = t & 255;
        unsigned long long acc[3][3];
        #pragma unroll
        for (int c = 0; c < 3; c++)
            #pragma unroll
            for (int k = 0; k < 3; k++) acc[c][k] = 0ull;
        float dloc = 0.f;
        __syncthreads();

        for (int cc = 0; cc < CPB; cc++) {
            int s0 = (cb + cc) * CHROWS;
            if (cc > 0) __syncthreads();   // protect x_s/e_s from prior phase 2

            // ---- phase 1: 32 rows x 16 lanes, float4 x loads + smem staging
            {
                int rw = t >> 4, p = t & 15;
                const float4* xr4 =
                    (const float4*)(x + ((size_t)b*SS + s0 + rw)*DM);
                float4* xs4 = (float4*)(x_s + rw*XPAD);
                unsigned long long a2[12];
                #pragma unroll
                for (int h = 0; h < 12; h++) a2[h] = 0ull;
                #pragma unroll
                for (int i = 0; i < 12; i++) {
                    int m4 = i*16 + p;
                    float4 xv = xr4[m4];
                    xs4[m4] = xv;
                    unsigned long long xlo, xhi;
                    PACK2(xlo, xv.x, xv.y);
                    PACK2(xhi, xv.z, xv.w);
                    #pragma unroll
                    for (int h = 0; h < 12; h++) {
                        const ulonglong2* up =
                            (const ulonglong2*)(u_s + h*DM + m4*4);
                        ulonglong2 uu = up[0];
                        FMA2(a2[h], xlo, uu.x, a2[h]);
                        FMA2(a2[h], xhi, uu.y, a2[h]);
                    }
                }
                float v[12];
                #pragma unroll
                for (int h = 0; h < 12; h++) {
                    float lo, hi;
                    UNPK2(lo, hi, a2[h]);
                    v[h] = lo + hi;
                }
                #pragma unroll
                for (int off = 8; off; off >>= 1)
                    #pragma unroll
                    for (int h = 0; h < 12; h++)
                        v[h] += __shfl_down_sync(0xffffffffu, v[h], off, 16);
                if (p == 0) {
                    #pragma unroll
                    for (int h = 0; h < 12; h++)
                        e_s[rw*HH + h] = __expf(v[h]);
                }
            }
            __syncthreads();

            // ---- denominator partial (local register accumulation)
            if (t < HH) {
                #pragma unroll 8
                for (int j = 0; j < CHROWS; j++) dloc += e_s[j*HH + t];
            }

            // ---- phase 2: y[h][m] += sum_s e[s][h]*x_s[s][m] (smem reads)
            {
                const float* xp = x_s;
                for (int s = 0; s < CHROWS; s++) {
                    float xv0 = xp[s*XPAD + tc];
                    float xv1 = xp[s*XPAD + 256 + tc];
                    float xv2 = xp[s*XPAD + 512 + tc];
                    unsigned long long xx0, xx1, xx2;
                    PACK2(xx0, xv0, xv0);
                    PACK2(xx1, xv1, xv1);
                    PACK2(xx2, xv2, xv2);
                    const unsigned long long* ep =
                        (const unsigned long long*)(e_s + s*HH + hh*6);
                    unsigned long long e0 = ep[0], e1 = ep[1], e2 = ep[2];
                    FMA2(acc[0][0], e0, xx0, acc[0][0]);
                    FMA2(acc[0][1], e1, xx0, acc[0][1]);
                    FMA2(acc[0][2], e2, xx0, acc[0][2]);
                    FMA2(acc[1][0], e0, xx1, acc[1][0]);
                    FMA2(acc[1][1], e1, xx1, acc[1][1]);
                    FMA2(acc[1][2], e2, xx1, acc[1][2]);
                    FMA2(acc[2][0], e0, xx2, acc[2][0]);
                    FMA2(acc[2][1], e1, xx2, acc[2][1]);
                    FMA2(acc[2][2], e2, xx2, acc[2][2]);
                }
            }
        }

        // ---- write this block's y slot (no atomics) + denom
        {
            size_t base = (size_t)blk*HH + hh*6;
            #pragma unroll
            for (int c = 0; c < 3; c++)
                #pragma unroll
                for (int k = 0; k < 3; k++) {
                    float f0, f1;
                    UNPK2(f0, f1, acc[c][k]);
                    g_y[(base + 2*k  )*DM + c*256 + tc] = f0;
                    g_y[(base + 2*k+1)*DM + c*256 + tc] = f1;
                }
        }
        if (t < HH) atomicAdd(&g_denom[b*HH + t], dloc);
    }
    gbar();

    // ======== Stage 3: og = (y/denom) @ wvg slice (96 blocks) ===============
    if (blk < 96) {
        int b = blk / 48; int r = blk % 48;
        int h = r >> 2; int sub = r & 3;                 // 4 subs of 192 m
        float* redR = sm;            // 384
        float* y_s  = sm + 384;      // 192
        float* redG = sm + 768;      // 512
        float inv = 1.f / __ldcg(&g_denom[b*HH + h]);
        if (t < 384) {
            int e = t % 192, prt = t / 192;              // 2 parts x 32 slots
            float s = 0.f;
            #pragma unroll 8
            for (int sl = b*64 + prt*32; sl < b*64 + prt*32 + 32; sl++)
                s += g_y[((size_t)sl*HH + h)*DM + sub*192 + e];
            redR[t] = s;
        }
        __syncthreads();
        if (t < 192) y_s[t] = (redR[t] + redR[192+t]) * inv;
        __syncthreads();
        int o = t & 63, q = t >> 6;          // 8 parts of 24 m
        float acc = 0.f;
        const float* wc = wvg + h*64 + o;
        #pragma unroll
        for (int j = 0; j < 24; j++) {
            int ml = q*24 + j;
            acc += y_s[ml] * wc[(size_t)(sub*192 + ml)*DM];
        }
        redG[t] = acc;
        __syncthreads();
        if (t < 64) {
            float s = 0.f;
            #pragma unroll
            for (int k = 0; k < 8; k++) s += redG[k*64 + t];
            atomicAdd(&g_og[b*DM + h*64 + t], s);
        }
    }
    gbar();

    // ======== Stage 4: attn0 partials: og @ wo (72 blocks) ==================
    if (blk < 72) {
        int b = blk / 36; int r = blk % 36;
        int oc = r / 12;  int mcp = r % 12;      // 64-m chunk
        float* in_s = sm;
        if (t < 64) in_s[t] = __ldcg(&g_og[b*DM + mcp*64 + t]);
        __syncthreads();
        int o = oc*256 + (t & 255), mh = t >> 8;
        float acc = 0.f;
        const float* wc = wo + o;
        #pragma unroll
        for (int j = 0; j < 32; j++)
            acc += in_s[mh*32 + j] * wc[(size_t)(mcp*64 + mh*32 + j)*DM];
        atomicAdd(&g_part1[b*DM + o], acc);
    }
    gbar();

    // ======== Stage 5: pre-tanh pooled partials: attn0 @ wp =================
    if (blk < 72) {
        int b = blk / 36; int r = blk % 36;
        int oc = r / 12;  int mcp = r % 12;
        float* in_s = sm;
        if (t < 64) in_s[t] = __ldcg(&g_part1[b*DM + mcp*64 + t]);
        __syncthreads();
        int o = oc*256 + (t & 255), mh = t >> 8;
        float acc = 0.f;
        const float* wc = wp + o;
        #pragma unroll
        for (int j = 0; j < 32; j++)
            acc += in_s[mh*32 + j] * wc[(size_t)(mcp*64 + mh*32 + j)*DM];
        atomicAdd(&g_part2[b*DM + o], acc);
    }
    gbar();

    // ======== Stage 6: out += tanh(part2) @ wfc (48 blocks) =================
    if (blk < 48) {
        int b = blk / 24; int r = blk % 24;
        int oc = r / 12;  int mcp = r % 12;
        float* in_s = sm;
        if (t < 64) in_s[t] = tanhf(__ldcg(&g_part2[b*DM + mcp*64 + t]));
        __syncthreads();
        int o = oc*256 + (t & 255), mh = t >> 8;
        float acc = 0.f;
        const float* wc = wfc + o;
        #pragma unroll
        for (int j = 0; j < 32; j++)
            acc += in_s[mh*32 + j] * wc[(size_t)(mcp*64 + mh*32 + j)*OUTN];
        atomicAdd(&out[b*OUTN + o], acc);
    }
}

// ---------------- launch ----------------------------------------------------
extern "C" void kernel_launch(void* const* d_in, const int* in_sizes, int n_in,
                              void* d_out, int out_size) {
    const float* x   = (const float*)d_in[0];
    const float* wqg = (const float*)d_in[7];
    const float* bqg = (const float*)d_in[8];
    const float* wkg = (const float*)d_in[9];
    const float* wvg = (const float*)d_in[11];
    const float* bvg = (const float*)d_in[12];
    const float* wo  = (const float*)d_in[13];
    const float* bo  = (const float*)d_in[14];
    const float* wp  = (const float*)d_in[15];
    const float* bp  = (const float*)d_in[16];
    const float* wfc = (const float*)d_in[17];
    const float* bfc = (const float*)d_in[18];
    float* out = (float*)d_out;

    const size_t smem = (size_t)(9216 + 24704 + 384) * sizeof(float); // 137216 B
    static int configured = 0;
    if (!configured) {
        cudaFuncSetAttribute(k_mega, cudaFuncAttributeMaxDynamicSharedMemorySize,
                             (int)smem);
        configured = 1;
    }
    k_mega<<<GRID, NTHR, smem>>>(x, wqg, bqg, wkg, wvg, bvg, wo, bo, wp, bp,
                                 wfc, bfc, out);
}